// round 9
// baseline (speedup 1.0000x reference)
#include <cuda_runtime.h>
#include <cuda_bf16.h>
#include <cstdint>
#include <math.h>

// ===========================================================================
// out = softmax((xWq+bq)(xWk+bk)^T / 32) (xWv+bv);  B=4, S=2048, D=H=1024
// tf32 mma.sync GEMMs, operands pre-rounded to tf32 (zero cvt in mainloop),
// LDS.64 fragment loads via k-slot remap + XOR-swizzled 128B-row tiles,
// 64x64 warp tiles (128 thr / 4 warps). This round: B fragments single-
// buffered with j-outer MMA order (register-pressure relief), fused W^T pass.
// ===========================================================================

#define BATCH 4
#define SEQ   2048
#define DIM   1024

__device__ float g_Q [BATCH * SEQ * DIM];
__device__ float g_K [BATCH * SEQ * DIM];
__device__ float g_V [BATCH * SEQ * DIM];
__device__ float g_S [BATCH * SEQ * SEQ];
__device__ float g_xr[BATCH * SEQ * DIM];    // x rounded; reused as V^T later
__device__ float g_Wt[3 * DIM * DIM];        // packed W^T: rows n(3072), cols k(1024)
__device__ float g_b [3 * DIM];              // packed bq|bk|bv

// ---------------- helpers ---------------------------------------------------
__device__ __forceinline__ uint32_t smem_u32(const void* p) {
    uint32_t a;
    asm("{ .reg .u64 t; cvta.to.shared.u64 t, %1; cvt.u32.u64 %0, t; }"
        : "=r"(a) : "l"(p));
    return a;
}
__device__ __forceinline__ void cp16(uint32_t saddr, const void* g) {
    asm volatile("cp.async.cg.shared.global [%0], [%1], 16;" :: "r"(saddr), "l"(g));
}
__device__ __forceinline__ float round_tf32(float x) {
    uint32_t r;
    asm("cvt.rna.tf32.f32 %0, %1;" : "=r"(r) : "f"(x));
    return __uint_as_float(r);
}
__device__ __forceinline__ void mma_tf32(float* c, const uint32_t* a, const uint32_t* b) {
    asm volatile(
        "mma.sync.aligned.m16n8k8.row.col.f32.tf32.tf32.f32 "
        "{%0,%1,%2,%3}, {%4,%5,%6,%7}, {%8,%9}, {%0,%1,%2,%3};"
        : "+f"(c[0]), "+f"(c[1]), "+f"(c[2]), "+f"(c[3])
        : "r"(a[0]), "r"(a[1]), "r"(a[2]), "r"(a[3]), "r"(b[0]), "r"(b[1]));
}

// ===========================================================================
// NT GEMM: C[M,N] = A[M,K] x B[N,K]^T, 128x128xKB32 CTA tiles, 128 threads,
// 4 warps as 2x2 with 64x64 warp tiles. 3-stage cp.async, XOR-swizzled
// 128B-row tiles. A fragments double-buffered across kk; B fragments
// single-buffered per kk with j-outer MMA ordering.
// MODE: 1 = *alpha, 2 = plain, 3 = fused QKV (+packed bias, tf32 round,
//       route to C0/C1/C2 by n0>>10)
// ===========================================================================
#define TM 128
#define TN 128
#define KB 32
#define ASTRIDE (TM * 32)
#define BSTRIDE (TN * 32)
#define GSMEM   (3 * (ASTRIDE + BSTRIDE) * 4)   // 98304 B

template <int MODE>
__global__ __launch_bounds__(128, 2)
void gemm_nt(const float* __restrict__ Abase, const float* __restrict__ Bbase,
             const float* __restrict__ bias,
             float* __restrict__ C0, float* __restrict__ C1, float* __restrict__ C2,
             int M, int N, int K, int ldc,
             long long sA, long long sB, long long sC, float alpha)
{
    extern __shared__ float sm[];
    const int tid  = threadIdx.x;
    const int wid  = tid >> 5;
    const int lane = tid & 31;
    const int gq = lane >> 2;
    const int tq = lane & 3;
    const int wm = (wid >> 1) * 64;     // 2x2 warp grid, 64x64 warp tiles
    const int wn = (wid & 1) * 64;
    const int axk = (gq & 3) << 2;

    const float* A = Abase + (long long)blockIdx.z * sA;
    const float* B = Bbase + (long long)blockIdx.z * sB;
    const int m0 = blockIdx.y * TM;
    const int n0 = blockIdx.x * TN;

    float* As = sm;
    float* Bs = sm + 3 * ASTRIDE;

    auto loadA = [&](int k0, int s) {
        float* dst = As + s * ASTRIDE;
        const float* src = A + (long long)m0 * K + k0;
#pragma unroll
        for (int j = 0; j < 8; j++) {
            int idx = j * 128 + tid;
            int r = idx >> 3, ch = idx & 7;
            int off = r * 32 + (((2 * ch) ^ ((r & 3) << 2)) << 1);
            cp16(smem_u32(dst + off), src + (long long)r * K + ch * 4);
        }
    };
    auto loadB = [&](int k0, int s) {
        float* dst = Bs + s * BSTRIDE;
        const float* src = B + (long long)n0 * K + k0;
#pragma unroll
        for (int j = 0; j < 8; j++) {
            int idx = j * 128 + tid;
            int r = idx >> 3, ch = idx & 7;
            int off = r * 32 + (((2 * ch) ^ ((r & 3) << 2)) << 1);
            cp16(smem_u32(dst + off), src + (long long)r * K + ch * 4);
        }
    };

    float acc[4][8][4] = {};

    const int nIter = K / KB;
    loadA(0, 0); loadB(0, 0);
    asm volatile("cp.async.commit_group;" ::: "memory");
    loadA(KB, 1); loadB(KB, 1);
    asm volatile("cp.async.commit_group;" ::: "memory");

    for (int it = 0; it < nIter; it++) {
        asm volatile("cp.async.wait_group 1;" ::: "memory");
        __syncthreads();

        if (it + 2 < nIter) {
            loadA((it + 2) * KB, (it + 2) % 3);
            loadB((it + 2) * KB, (it + 2) % 3);
        }
        asm volatile("cp.async.commit_group;" ::: "memory");

        const float* a_s = As + (it % 3) * ASTRIDE;
        const float* b_s = Bs + (it % 3) * BSTRIDE;

        uint32_t af[2][4][4];                 // A double-buffered across kk
        auto ldfragA = [&](int kk, uint32_t (&afx)[4][4]) {
            const int cA = (((kk << 2) + tq) ^ axk) << 1;
#pragma unroll
            for (int i = 0; i < 4; i++) {
                const float* ap = a_s + (wm + i * 16 + gq) * 32 + cA;
                uint2 u0 = *reinterpret_cast<const uint2*>(ap);
                uint2 u1 = *reinterpret_cast<const uint2*>(ap + 8 * 32);
                afx[i][0] = u0.x; afx[i][1] = u1.x;
                afx[i][2] = u0.y; afx[i][3] = u1.y;
            }
        };

        ldfragA(0, af[0]);
#pragma unroll
        for (int kk = 0; kk < 4; kk++) {
            const int cA = (((kk << 2) + tq) ^ axk) << 1;
            uint32_t bf[8][2];                // B single-buffered per kk
#pragma unroll
            for (int j = 0; j < 8; j++) {
                const float* bp = b_s + (wn + j * 8 + gq) * 32 + cA;
                uint2 v = *reinterpret_cast<const uint2*>(bp);
                bf[j][0] = v.x; bf[j][1] = v.y;
            }
            if (kk < 3) ldfragA(kk + 1, af[(kk + 1) & 1]);
            // j-outer: bf[j] consumed in bursts of 4 MMAs, letting later
            // bf loads overlap earlier columns' MMA issue.
#pragma unroll
            for (int j = 0; j < 8; j++)
#pragma unroll
                for (int i = 0; i < 4; i++)
                    mma_tf32(acc[i][j], af[kk & 1][i], bf[j]);
        }
    }

    // epilogue
    float* Cw;
    int cshift = 0;
    if (MODE == 3) {
        const int mat = n0 >> 10;
        Cw = (mat == 0) ? C0 : (mat == 1) ? C1 : C2;
        cshift = n0 & ~1023;
    } else {
        Cw = C0 + (long long)blockIdx.z * sC;
    }
#pragma unroll
    for (int i = 0; i < 4; i++) {
#pragma unroll
        for (int j = 0; j < 8; j++) {
            const int r = m0 + wm + i * 16 + gq;
            const int c = n0 + wn + j * 8 + 2 * tq;
            float2 v0 = make_float2(acc[i][j][0], acc[i][j][1]);
            float2 v1 = make_float2(acc[i][j][2], acc[i][j][3]);
            if (MODE == 3) {
                float2 bz2 = *reinterpret_cast<const float2*>(bias + c);
                v0.x = round_tf32(v0.x + bz2.x);
                v0.y = round_tf32(v0.y + bz2.y);
                v1.x = round_tf32(v1.x + bz2.x);
                v1.y = round_tf32(v1.y + bz2.y);
            }
            if (MODE == 1) {
                v0.x *= alpha; v0.y *= alpha;
                v1.x *= alpha; v1.y *= alpha;
            }
            const int cc = c - cshift;
            *reinterpret_cast<float2*>(Cw + (long long)r * ldc + cc) = v0;
            *reinterpret_cast<float2*>(Cw + (long long)(r + 8) * ldc + cc) = v1;
        }
    }
}

// ---------------------------------------------------------------------------
// tf32 rounding + transpose utilities
// ---------------------------------------------------------------------------
__global__ __launch_bounds__(256)
void round_pass(const float* __restrict__ src, float* __restrict__ dst)
{
    int idx = blockIdx.x * 256 + threadIdx.x;
    float4 v = reinterpret_cast<const float4*>(src)[idx];
    v.x = round_tf32(v.x); v.y = round_tf32(v.y);
    v.z = round_tf32(v.z); v.w = round_tf32(v.w);
    reinterpret_cast<float4*>(dst)[idx] = v;
}

// transpose [R,C] -> out[C,R], z-slices select input/output offsets.
template <bool ROUND>
__global__ void transp32(const float* __restrict__ in, float* __restrict__ out,
                         int R, int C, long long sIn, long long sOut, int rowOffMul)
{
    __shared__ float t[32][33];
    in  += (long long)blockIdx.z * sIn;
    out += (long long)blockIdx.z * sOut;
    const int rowOff = blockIdx.z * rowOffMul;
    int r0 = blockIdx.y * 32, c0 = blockIdx.x * 32;
    int tx = threadIdx.x, ty = threadIdx.y;
#pragma unroll
    for (int i = 0; i < 4; i++)
        t[ty + i * 8][tx] = in[(long long)(r0 + ty + i * 8) * C + c0 + tx];
    __syncthreads();
#pragma unroll
    for (int i = 0; i < 4; i++) {
        int oc = ty + i * 8;
        float v = t[tx][oc];
        if (ROUND) v = round_tf32(v);
        out[(long long)(rowOff + c0 + oc) * R + r0 + tx] = v;
    }
}

__global__ void pack_bias(const float* __restrict__ b0, const float* __restrict__ b1,
                          const float* __restrict__ b2, float* __restrict__ dst)
{
    int t = threadIdx.x + blockIdx.x * 1024;
    const float* s = (blockIdx.x == 0) ? b0 : (blockIdx.x == 1) ? b1 : b2;
    dst[t] = s[threadIdx.x];
}

// ---------------------------------------------------------------------------
// Row softmax (rows of 2048), 256 threads, warp-shuffle reduce, tf32 out.
// ---------------------------------------------------------------------------
__global__ __launch_bounds__(256)
void softmax_rows(float* __restrict__ S)
{
    float4* row4 = reinterpret_cast<float4*>(S + (long long)blockIdx.x * SEQ);
    __shared__ float red[8];
    const int t = threadIdx.x;
    const int wid = t >> 5, lane = t & 31;

    float4 a = row4[t];
    float4 b = row4[t + 256];
    float mx = fmaxf(fmaxf(fmaxf(a.x, a.y), fmaxf(a.z, a.w)),
                     fmaxf(fmaxf(b.x, b.y), fmaxf(b.z, b.w)));
#pragma unroll
    for (int s = 16; s > 0; s >>= 1)
        mx = fmaxf(mx, __shfl_xor_sync(0xffffffffu, mx, s));
    if (lane == 0) red[wid] = mx;
    __syncthreads();
    mx = red[0];
#pragma unroll
    for (int i = 1; i < 8; i++) mx = fmaxf(mx, red[i]);

    a.x = __expf(a.x - mx); a.y = __expf(a.y - mx);
    a.z = __expf(a.z - mx); a.w = __expf(a.w - mx);
    b.x = __expf(b.x - mx); b.y = __expf(b.y - mx);
    b.z = __expf(b.z - mx); b.w = __expf(b.w - mx);
    float sum = (a.x + a.y) + (a.z + a.w) + (b.x + b.y) + (b.z + b.w);
#pragma unroll
    for (int s = 16; s > 0; s >>= 1)
        sum += __shfl_xor_sync(0xffffffffu, sum, s);
    __syncthreads();
    if (lane == 0) red[wid] = sum;
    __syncthreads();
    sum = red[0];
#pragma unroll
    for (int i = 1; i < 8; i++) sum += red[i];
    float inv = 1.0f / sum;

    a.x = round_tf32(a.x * inv); a.y = round_tf32(a.y * inv);
    a.z = round_tf32(a.z * inv); a.w = round_tf32(a.w * inv);
    b.x = round_tf32(b.x * inv); b.y = round_tf32(b.y * inv);
    b.z = round_tf32(b.z * inv); b.w = round_tf32(b.w * inv);
    row4[t] = a;
    row4[t + 256] = b;
}

// ---------------------------------------------------------------------------
extern "C" void kernel_launch(void* const* d_in, const int* in_sizes, int n_in,
                              void* d_out, int out_size)
{
    const float* x  = (const float*)d_in[0];
    const float* Wq = (const float*)d_in[1];
    const float* bq = (const float*)d_in[2];
    const float* Wk = (const float*)d_in[3];
    const float* bk = (const float*)d_in[4];
    const float* Wv = (const float*)d_in[5];
    const float* bv = (const float*)d_in[6];
    float* out = (float*)d_out;

    static float *pQ = nullptr, *pK = nullptr, *pV = nullptr, *pS = nullptr,
                 *pxr = nullptr, *pWt = nullptr, *pb = nullptr;
    if (!pQ) {
        cudaGetSymbolAddress((void**)&pQ,  g_Q);
        cudaGetSymbolAddress((void**)&pK,  g_K);
        cudaGetSymbolAddress((void**)&pV,  g_V);
        cudaGetSymbolAddress((void**)&pS,  g_S);
        cudaGetSymbolAddress((void**)&pxr, g_xr);
        cudaGetSymbolAddress((void**)&pWt, g_Wt);
        cudaGetSymbolAddress((void**)&pb,  g_b);
        cudaFuncSetAttribute(gemm_nt<3>, cudaFuncAttributeMaxDynamicSharedMemorySize, GSMEM);
        cudaFuncSetAttribute(gemm_nt<1>, cudaFuncAttributeMaxDynamicSharedMemorySize, GSMEM);
        cudaFuncSetAttribute(gemm_nt<2>, cudaFuncAttributeMaxDynamicSharedMemorySize, GSMEM);
    }

    const int M = BATCH * SEQ;          // 8192
    const float scale = 0.03125f;       // 1/sqrt(1024)
    dim3 tb(32, 8);

    // 0) pre-round x; W^T packed+rounded (one z=3 launch: Wq|Wk|Wv are the
    //    harness's d_in[1,3,5] — NOT contiguous, so index via Wq only when
    //    contiguity is known; use separate pointers through a strided trick:
    //    launch one kernel per W is avoided by passing base=Wq is unsafe, so
    //    keep correctness: z selects the source pointer inside the kernel is
    //    not possible without an array. Use 3 small launches only for safety
    //    where layout is unknown -> fall back to explicit per-W z=1 launches.
    round_pass<<<M * DIM / 1024, 256>>>(x, pxr);
    transp32<true><<<dim3(32, 32, 1), tb>>>(Wq, pWt, DIM, DIM, 0, 0, 0);
    transp32<true><<<dim3(32, 32, 1), tb>>>(Wk, pWt + (long long)DIM * DIM, DIM, DIM, 0, 0, 0);
    transp32<true><<<dim3(32, 32, 1), tb>>>(Wv, pWt + 2LL * DIM * DIM, DIM, DIM, 0, 0, 0);
    pack_bias<<<3, 1024>>>(bq, bk, bv, pb);

    // 1) fused QKV projection: [8192,1024] x W^T[3072,1024] -> Q,K,V
    gemm_nt<3><<<dim3(3072 / TN, M / TM, 1), 128, GSMEM>>>(
        pxr, pWt, pb, pQ, pK, pV, M, 3072, DIM, DIM, 0, 0, 0, 1.f);

    // 1b) V^T per batch: [2048,1024] -> [1024,2048]  (into pxr, now free)
    transp32<false><<<dim3(32, 64, BATCH), tb>>>(
        pV, pxr, SEQ, DIM, (long long)SEQ * DIM, (long long)DIM * SEQ, 0);

    // 2) scores = Q K^T * scale (per batch, NT)
    gemm_nt<1><<<dim3(SEQ / TN, SEQ / TM, BATCH), 128, GSMEM>>>(
        pQ, pK, nullptr, pS, nullptr, nullptr,
        SEQ, SEQ, DIM, SEQ,
        (long long)SEQ * DIM, (long long)SEQ * DIM, (long long)SEQ * SEQ, scale);

    // 3) softmax rows (in place, tf32-rounded)
    softmax_rows<<<BATCH * SEQ, 256>>>(pS);

    // 4) out = P V  = P x (V^T)^T (per batch, NT)
    gemm_nt<2><<<dim3(DIM / TN, SEQ / TM, BATCH), 128, GSMEM>>>(
        pS, pxr, nullptr, out, nullptr, nullptr,
        SEQ, DIM, SEQ, DIM,
        (long long)SEQ * SEQ, (long long)DIM * SEQ, (long long)SEQ * DIM, 1.f);
}

// round 10
// speedup vs baseline: 1.1095x; 1.1095x over previous
#include <cuda_runtime.h>
#include <cuda_bf16.h>
#include <cstdint>
#include <math.h>

// ===========================================================================
// out = softmax((xWq+bq)(xWk+bk)^T / 32) (xWv+bv);  B=4, S=2048, D=H=1024
// tf32 mma.sync GEMMs, operands pre-rounded to tf32 (zero cvt in mainloop),
// LDS.64 fragment loads via k-slot remap + XOR-swizzled 128B-row tiles,
// 64x64 warp tiles (128 thr / 4 warps), A+B fragments double-buffered
// across kk (R8 configuration — best known). Merged W^T preprocessing.
// ===========================================================================

#define BATCH 4
#define SEQ   2048
#define DIM   1024

__device__ float g_Q [BATCH * SEQ * DIM];
__device__ float g_K [BATCH * SEQ * DIM];
__device__ float g_V [BATCH * SEQ * DIM];
__device__ float g_S [BATCH * SEQ * SEQ];
__device__ float g_xr[BATCH * SEQ * DIM];    // x rounded; reused as V^T later
__device__ float g_Wt[3 * DIM * DIM];        // packed W^T: rows n(3072), cols k(1024)
__device__ float g_b [3 * DIM];              // packed bq|bk|bv

// ---------------- helpers ---------------------------------------------------
__device__ __forceinline__ uint32_t smem_u32(const void* p) {
    uint32_t a;
    asm("{ .reg .u64 t; cvta.to.shared.u64 t, %1; cvt.u32.u64 %0, t; }"
        : "=r"(a) : "l"(p));
    return a;
}
__device__ __forceinline__ void cp16(uint32_t saddr, const void* g) {
    asm volatile("cp.async.cg.shared.global [%0], [%1], 16;" :: "r"(saddr), "l"(g));
}
__device__ __forceinline__ float round_tf32(float x) {
    uint32_t r;
    asm("cvt.rna.tf32.f32 %0, %1;" : "=r"(r) : "f"(x));
    return __uint_as_float(r);
}
__device__ __forceinline__ void mma_tf32(float* c, const uint32_t* a, const uint32_t* b) {
    asm volatile(
        "mma.sync.aligned.m16n8k8.row.col.f32.tf32.tf32.f32 "
        "{%0,%1,%2,%3}, {%4,%5,%6,%7}, {%8,%9}, {%0,%1,%2,%3};"
        : "+f"(c[0]), "+f"(c[1]), "+f"(c[2]), "+f"(c[3])
        : "r"(a[0]), "r"(a[1]), "r"(a[2]), "r"(a[3]), "r"(b[0]), "r"(b[1]));
}

// ===========================================================================
// NT GEMM: C[M,N] = A[M,K] x B[N,K]^T, 128x128xKB32 CTA tiles, 128 threads,
// 4 warps as 2x2 with 64x64 warp tiles. 3-stage cp.async, XOR-swizzled
// 128B-row tiles, A+B fragments double-buffered across kk (ping-pong).
// MODE: 1 = *alpha, 2 = plain, 3 = fused QKV (+packed bias, tf32 round,
//       route to C0/C1/C2 by n0>>10)
// ===========================================================================
#define TM 128
#define TN 128
#define KB 32
#define ASTRIDE (TM * 32)
#define BSTRIDE (TN * 32)
#define GSMEM   (3 * (ASTRIDE + BSTRIDE) * 4)   // 98304 B

template <int MODE>
__global__ __launch_bounds__(128, 2)
void gemm_nt(const float* __restrict__ Abase, const float* __restrict__ Bbase,
             const float* __restrict__ bias,
             float* __restrict__ C0, float* __restrict__ C1, float* __restrict__ C2,
             int M, int N, int K, int ldc,
             long long sA, long long sB, long long sC, float alpha)
{
    extern __shared__ float sm[];
    const int tid  = threadIdx.x;
    const int wid  = tid >> 5;
    const int lane = tid & 31;
    const int gq = lane >> 2;
    const int tq = lane & 3;
    const int wm = (wid >> 1) * 64;     // 2x2 warp grid, 64x64 warp tiles
    const int wn = (wid & 1) * 64;
    const int axk = (gq & 3) << 2;

    const float* A = Abase + (long long)blockIdx.z * sA;
    const float* B = Bbase + (long long)blockIdx.z * sB;
    const int m0 = blockIdx.y * TM;
    const int n0 = blockIdx.x * TN;

    float* As = sm;
    float* Bs = sm + 3 * ASTRIDE;

    auto loadA = [&](int k0, int s) {
        float* dst = As + s * ASTRIDE;
        const float* src = A + (long long)m0 * K + k0;
#pragma unroll
        for (int j = 0; j < 8; j++) {
            int idx = j * 128 + tid;
            int r = idx >> 3, ch = idx & 7;
            int off = r * 32 + (((2 * ch) ^ ((r & 3) << 2)) << 1);
            cp16(smem_u32(dst + off), src + (long long)r * K + ch * 4);
        }
    };
    auto loadB = [&](int k0, int s) {
        float* dst = Bs + s * BSTRIDE;
        const float* src = B + (long long)n0 * K + k0;
#pragma unroll
        for (int j = 0; j < 8; j++) {
            int idx = j * 128 + tid;
            int r = idx >> 3, ch = idx & 7;
            int off = r * 32 + (((2 * ch) ^ ((r & 3) << 2)) << 1);
            cp16(smem_u32(dst + off), src + (long long)r * K + ch * 4);
        }
    };

    float acc[4][8][4] = {};

    const int nIter = K / KB;
    loadA(0, 0); loadB(0, 0);
    asm volatile("cp.async.commit_group;" ::: "memory");
    loadA(KB, 1); loadB(KB, 1);
    asm volatile("cp.async.commit_group;" ::: "memory");

    for (int it = 0; it < nIter; it++) {
        asm volatile("cp.async.wait_group 1;" ::: "memory");
        __syncthreads();

        if (it + 2 < nIter) {
            loadA((it + 2) * KB, (it + 2) % 3);
            loadB((it + 2) * KB, (it + 2) % 3);
        }
        asm volatile("cp.async.commit_group;" ::: "memory");

        const float* a_s = As + (it % 3) * ASTRIDE;
        const float* b_s = Bs + (it % 3) * BSTRIDE;

        uint32_t af[2][4][4];
        uint32_t bf[2][8][2];
        auto ldfrag = [&](int kk, uint32_t (&afx)[4][4], uint32_t (&bfx)[8][2]) {
            const int cA = (((kk << 2) + tq) ^ axk) << 1;
#pragma unroll
            for (int i = 0; i < 4; i++) {
                const float* ap = a_s + (wm + i * 16 + gq) * 32 + cA;
                uint2 u0 = *reinterpret_cast<const uint2*>(ap);
                uint2 u1 = *reinterpret_cast<const uint2*>(ap + 8 * 32);
                afx[i][0] = u0.x; afx[i][1] = u1.x;
                afx[i][2] = u0.y; afx[i][3] = u1.y;
            }
#pragma unroll
            for (int j = 0; j < 8; j++) {
                const float* bp = b_s + (wn + j * 8 + gq) * 32 + cA;
                uint2 v = *reinterpret_cast<const uint2*>(bp);
                bfx[j][0] = v.x; bfx[j][1] = v.y;
            }
        };

        ldfrag(0, af[0], bf[0]);
#pragma unroll
        for (int kk = 0; kk < 4; kk++) {
            if (kk < 3) ldfrag(kk + 1, af[(kk + 1) & 1], bf[(kk + 1) & 1]);
#pragma unroll
            for (int i = 0; i < 4; i++)
#pragma unroll
                for (int j = 0; j < 8; j++)
                    mma_tf32(acc[i][j], af[kk & 1][i], bf[kk & 1][j]);
        }
    }

    // epilogue
    float* Cw;
    int cshift = 0;
    if (MODE == 3) {
        const int mat = n0 >> 10;
        Cw = (mat == 0) ? C0 : (mat == 1) ? C1 : C2;
        cshift = n0 & ~1023;
    } else {
        Cw = C0 + (long long)blockIdx.z * sC;
    }
#pragma unroll
    for (int i = 0; i < 4; i++) {
#pragma unroll
        for (int j = 0; j < 8; j++) {
            const int r = m0 + wm + i * 16 + gq;
            const int c = n0 + wn + j * 8 + 2 * tq;
            float2 v0 = make_float2(acc[i][j][0], acc[i][j][1]);
            float2 v1 = make_float2(acc[i][j][2], acc[i][j][3]);
            if (MODE == 3) {
                float2 bz2 = *reinterpret_cast<const float2*>(bias + c);
                v0.x = round_tf32(v0.x + bz2.x);
                v0.y = round_tf32(v0.y + bz2.y);
                v1.x = round_tf32(v1.x + bz2.x);
                v1.y = round_tf32(v1.y + bz2.y);
            }
            if (MODE == 1) {
                v0.x *= alpha; v0.y *= alpha;
                v1.x *= alpha; v1.y *= alpha;
            }
            const int cc = c - cshift;
            *reinterpret_cast<float2*>(Cw + (long long)r * ldc + cc) = v0;
            *reinterpret_cast<float2*>(Cw + (long long)(r + 8) * ldc + cc) = v1;
        }
    }
}

// ---------------------------------------------------------------------------
// tf32 rounding + transpose utilities
// ---------------------------------------------------------------------------
__global__ __launch_bounds__(256)
void round_pass(const float* __restrict__ src, float* __restrict__ dst)
{
    int idx = blockIdx.x * 256 + threadIdx.x;
    float4 v = reinterpret_cast<const float4*>(src)[idx];
    v.x = round_tf32(v.x); v.y = round_tf32(v.y);
    v.z = round_tf32(v.z); v.w = round_tf32(v.w);
    reinterpret_cast<float4*>(dst)[idx] = v;
}

// transpose+round all three W [1024,1024] into packed W^T [3072,1024];
// blockIdx.z selects the source weight matrix.
__global__ void transp_w3(const float* __restrict__ w0, const float* __restrict__ w1,
                          const float* __restrict__ w2, float* __restrict__ out)
{
    __shared__ float t[32][33];
    const float* in = (blockIdx.z == 0) ? w0 : (blockIdx.z == 1) ? w1 : w2;
    float* o = out + (long long)blockIdx.z * DIM * DIM;
    int r0 = blockIdx.y * 32, c0 = blockIdx.x * 32;
    int tx = threadIdx.x, ty = threadIdx.y;
#pragma unroll
    for (int i = 0; i < 4; i++)
        t[ty + i * 8][tx] = in[(long long)(r0 + ty + i * 8) * DIM + c0 + tx];
    __syncthreads();
#pragma unroll
    for (int i = 0; i < 4; i++) {
        int oc = ty + i * 8;
        o[(long long)(c0 + oc) * DIM + r0 + tx] = round_tf32(t[tx][oc]);
    }
}

// transpose V per batch: [2048,1024] -> [1024,2048]
__global__ void transp_v(const float* __restrict__ in, float* __restrict__ out)
{
    __shared__ float t[32][33];
    in  += (long long)blockIdx.z * SEQ * DIM;
    out += (long long)blockIdx.z * DIM * SEQ;
    int r0 = blockIdx.y * 32, c0 = blockIdx.x * 32;
    int tx = threadIdx.x, ty = threadIdx.y;
#pragma unroll
    for (int i = 0; i < 4; i++)
        t[ty + i * 8][tx] = in[(long long)(r0 + ty + i * 8) * DIM + c0 + tx];
    __syncthreads();
#pragma unroll
    for (int i = 0; i < 4; i++) {
        int oc = ty + i * 8;
        out[(long long)(c0 + oc) * SEQ + r0 + tx] = t[tx][oc];
    }
}

__global__ void pack_bias(const float* __restrict__ b0, const float* __restrict__ b1,
                          const float* __restrict__ b2, float* __restrict__ dst)
{
    int t = threadIdx.x + blockIdx.x * 1024;
    const float* s = (blockIdx.x == 0) ? b0 : (blockIdx.x == 1) ? b1 : b2;
    dst[t] = s[threadIdx.x];
}

// ---------------------------------------------------------------------------
// Row softmax (rows of 2048), 256 threads, warp-shuffle reduce, tf32 out.
// ---------------------------------------------------------------------------
__global__ __launch_bounds__(256)
void softmax_rows(float* __restrict__ S)
{
    float4* row4 = reinterpret_cast<float4*>(S + (long long)blockIdx.x * SEQ);
    __shared__ float red[8];
    const int t = threadIdx.x;
    const int wid = t >> 5, lane = t & 31;

    float4 a = row4[t];
    float4 b = row4[t + 256];
    float mx = fmaxf(fmaxf(fmaxf(a.x, a.y), fmaxf(a.z, a.w)),
                     fmaxf(fmaxf(b.x, b.y), fmaxf(b.z, b.w)));
#pragma unroll
    for (int s = 16; s > 0; s >>= 1)
        mx = fmaxf(mx, __shfl_xor_sync(0xffffffffu, mx, s));
    if (lane == 0) red[wid] = mx;
    __syncthreads();
    mx = red[0];
#pragma unroll
    for (int i = 1; i < 8; i++) mx = fmaxf(mx, red[i]);

    a.x = __expf(a.x - mx); a.y = __expf(a.y - mx);
    a.z = __expf(a.z - mx); a.w = __expf(a.w - mx);
    b.x = __expf(b.x - mx); b.y = __expf(b.y - mx);
    b.z = __expf(b.z - mx); b.w = __expf(b.w - mx);
    float sum = (a.x + a.y) + (a.z + a.w) + (b.x + b.y) + (b.z + b.w);
#pragma unroll
    for (int s = 16; s > 0; s >>= 1)
        sum += __shfl_xor_sync(0xffffffffu, sum, s);
    __syncthreads();
    if (lane == 0) red[wid] = sum;
    __syncthreads();
    sum = red[0];
#pragma unroll
    for (int i = 1; i < 8; i++) sum += red[i];
    float inv = 1.0f / sum;

    a.x = round_tf32(a.x * inv); a.y = round_tf32(a.y * inv);
    a.z = round_tf32(a.z * inv); a.w = round_tf32(a.w * inv);
    b.x = round_tf32(b.x * inv); b.y = round_tf32(b.y * inv);
    b.z = round_tf32(b.z * inv); b.w = round_tf32(b.w * inv);
    row4[t] = a;
    row4[t + 256] = b;
}

// ---------------------------------------------------------------------------
extern "C" void kernel_launch(void* const* d_in, const int* in_sizes, int n_in,
                              void* d_out, int out_size)
{
    const float* x  = (const float*)d_in[0];
    const float* Wq = (const float*)d_in[1];
    const float* bq = (const float*)d_in[2];
    const float* Wk = (const float*)d_in[3];
    const float* bk = (const float*)d_in[4];
    const float* Wv = (const float*)d_in[5];
    const float* bv = (const float*)d_in[6];
    float* out = (float*)d_out;

    static float *pQ = nullptr, *pK = nullptr, *pV = nullptr, *pS = nullptr,
                 *pxr = nullptr, *pWt = nullptr, *pb = nullptr;
    if (!pQ) {
        cudaGetSymbolAddress((void**)&pQ,  g_Q);
        cudaGetSymbolAddress((void**)&pK,  g_K);
        cudaGetSymbolAddress((void**)&pV,  g_V);
        cudaGetSymbolAddress((void**)&pS,  g_S);
        cudaGetSymbolAddress((void**)&pxr, g_xr);
        cudaGetSymbolAddress((void**)&pWt, g_Wt);
        cudaGetSymbolAddress((void**)&pb,  g_b);
        cudaFuncSetAttribute(gemm_nt<3>, cudaFuncAttributeMaxDynamicSharedMemorySize, GSMEM);
        cudaFuncSetAttribute(gemm_nt<1>, cudaFuncAttributeMaxDynamicSharedMemorySize, GSMEM);
        cudaFuncSetAttribute(gemm_nt<2>, cudaFuncAttributeMaxDynamicSharedMemorySize, GSMEM);
    }

    const int M = BATCH * SEQ;          // 8192
    const float scale = 0.03125f;       // 1/sqrt(1024)
    dim3 tb(32, 8);

    // 0) pre-round x; W^T packed+rounded (single z=3 launch); bias packed
    round_pass<<<M * DIM / 1024, 256>>>(x, pxr);
    transp_w3<<<dim3(32, 32, 3), tb>>>(Wq, Wk, Wv, pWt);
    pack_bias<<<3, 1024>>>(bq, bk, bv, pb);

    // 1) fused QKV projection: [8192,1024] x W^T[3072,1024] -> Q,K,V
    gemm_nt<3><<<dim3(3072 / TN, M / TM, 1), 128, GSMEM>>>(
        pxr, pWt, pb, pQ, pK, pV, M, 3072, DIM, DIM, 0, 0, 0, 1.f);

    // 1b) V^T per batch: [2048,1024] -> [1024,2048]  (into pxr, now free)
    transp_v<<<dim3(32, 64, BATCH), tb>>>(pV, pxr);

    // 2) scores = Q K^T * scale (per batch, NT)
    gemm_nt<1><<<dim3(SEQ / TN, SEQ / TM, BATCH), 128, GSMEM>>>(
        pQ, pK, nullptr, pS, nullptr, nullptr,
        SEQ, SEQ, DIM, SEQ,
        (long long)SEQ * DIM, (long long)SEQ * DIM, (long long)SEQ * SEQ, scale);

    // 3) softmax rows (in place, tf32-rounded)
    softmax_rows<<<BATCH * SEQ, 256>>>(pS);

    // 4) out = P V  = P x (V^T)^T (per batch, NT)
    gemm_nt<2><<<dim3(DIM / TN, SEQ / TM, BATCH), 128, GSMEM>>>(
        pS, pxr, nullptr, out, nullptr, nullptr,
        SEQ, DIM, SEQ, DIM,
        (long long)SEQ * SEQ, (long long)DIM * SEQ, (long long)SEQ * DIM, 1.f);
}